// round 3
// baseline (speedup 1.0000x reference)
#include <cuda_runtime.h>
#include <cuda_bf16.h>
#include <cstdint>

// FirstSpikeDetector: out[b][t] = 1 iff spike_train[b][t] is the first nonzero
// in row b, else 0. Input values are exact 0.0f / 1.0f.
//
// R3: revert the R2 .cs/.ldcs regression (plain STG.128/LDG.128), switch to an
// exactly-resident persistent grid (148 SMs x 8 blocks x 8 warps) with a
// row-stride loop per warp. Each warp, per row:
//   1. load the first 128 elements (32 x float4),
//   2. stream zeros to vectors 32..511 (independent of the load),
//   3. ballot -> one-hot store of vector [0..31],
//   4. (P ~ 1.4e-6) rare path: continue the scan, fence, scalar overwrite.
// Traffic: 128MB compulsory write + ~8MB read -> steady-state HBM-write bound.

static constexpr int T  = 2048;   // time steps per row
static constexpr int TV = T / 4;  // float4s per row (512)

__global__ void __launch_bounds__(256)
first_spike_kernel(const float* __restrict__ in, float* __restrict__ out,
                   int rows, int total_warps)
{
    const int gtid  = blockIdx.x * blockDim.x + threadIdx.x;
    const int warp0 = gtid >> 5;
    const int lane  = gtid & 31;

    const float4 z = make_float4(0.0f, 0.0f, 0.0f, 0.0f);

    for (int row = warp0; row < rows; row += total_warps) {
        const float4* __restrict__ row_in  =
            reinterpret_cast<const float4*>(in)  + (size_t)row * TV;
        float4* __restrict__ row_out =
            reinterpret_cast<float4*>(out) + (size_t)row * TV;

        // Scan load for the first 128 elements (vectors 0..31).
        float4 v = row_in[lane];

        // Independent zero stream for vectors 32..511 while the load is in flight.
        #pragma unroll
        for (int i = 32 + lane; i < TV; i += 32) {
            row_out[i] = z;
        }

        const bool any = (v.x != 0.0f) | (v.y != 0.0f) | (v.z != 0.0f) | (v.w != 0.0f);
        const unsigned m = __ballot_sync(0xffffffffu, any);

        if (m != 0u) {
            // Common path: first spike is within the first 128 elements.
            const int src = __ffs(m) - 1;
            float4 w = z;
            if (lane == src) {
                int sub;
                if      (v.x != 0.0f) sub = 0;
                else if (v.y != 0.0f) sub = 1;
                else if (v.z != 0.0f) sub = 2;
                else                  sub = 3;
                (&w.x)[sub] = 1.0f;
            }
            row_out[lane] = w;
        } else {
            // Rare path (P ~ 1.4e-6 per row): zero vectors 0..31, keep scanning.
            row_out[lane] = z;

            int first = -1;
            #pragma unroll 1
            for (int base = 128; base < T; base += 128) {
                float4 u = row_in[(base >> 2) + lane];
                bool a2 = (u.x != 0.0f) | (u.y != 0.0f) | (u.z != 0.0f) | (u.w != 0.0f);
                unsigned m2 = __ballot_sync(0xffffffffu, a2);
                if (m2) {
                    int s2 = __ffs(m2) - 1;
                    if (lane == s2) {
                        int sub;
                        if      (u.x != 0.0f) sub = 0;
                        else if (u.y != 0.0f) sub = 1;
                        else if (u.z != 0.0f) sub = 2;
                        else                  sub = 3;
                        first = base + (s2 << 2) + sub;
                    }
                    break;   // m2 is warp-uniform; all lanes exit together
                }
            }

            __syncwarp();   // order the zero stores before the scalar overwrite
            if (first >= 0) {
                reinterpret_cast<float*>(row_out)[first] = 1.0f;
            }
        }
    }
}

extern "C" void kernel_launch(void* const* d_in, const int* in_sizes, int n_in,
                              void* d_out, int out_size)
{
    const float* in = (const float*)d_in[0];
    float* out = (float*)d_out;

    const int rows = in_sizes[0] / T;     // 16384

    const int threads = 256;              // 8 warps/block
    const int blocks  = 148 * 8;          // exactly resident: 8 blocks/SM
    const int total_warps = blocks * (threads / 32);  // 9472

    first_spike_kernel<<<blocks, threads>>>(in, out, rows, total_warps);
}